// round 7
// baseline (speedup 1.0000x reference)
#include <cuda_runtime.h>
#include <cstdint>

#define B_ 8
#define L_ 8192
#define H_ 128
#define N_ 32
#define G_ 256   /* 2H */
#define TC 64    /* chunk length */
#define J_ 128   /* chunks */
#define COLS 1024 /* B_*J_ columns per head */

typedef unsigned long long ull;

// Scratch (static __device__ arrays: no allocation anywhere)
__device__ float4 g_wk[H_ * N_];                 // {w_re, w_im, k_re, k_im}
__device__ float2 g_wT[H_ * N_];                 // w^64
__device__ __align__(16) ull g_A1[(size_t)H_ * TC * TC];        // finals matrix  [h][k][row] dup'd
__device__ __align__(16) ull g_A2[(size_t)H_ * 2 * TC * TC];    // [Tri|V]        [h][k][row] dup'd
__device__ float  g_F[(size_t)H_ * COLS * TC];   // chunk-local finals  [h][col][row]
__device__ float  g_C[(size_t)H_ * COLS * TC];   // carries             [h][col][row]
__device__ float  g_y[(size_t)B_ * H_ * L_];     // post-GELU activations (B,H,L)
__device__ __align__(16) ull g_wt2[H_ * G_];     // out_w transposed + dup'd
__device__ float  g_pooled[B_ * H_];

__device__ __forceinline__ ull fma2(ull a, ull b, ull c) {
    ull d; asm("fma.rn.f32x2 %0,%1,%2,%3;" : "=l"(d) : "l"(a), "l"(b), "l"(c)); return d;
}
__device__ __forceinline__ ull pack2(float x, float y) {
    ull d; asm("mov.b64 %0,{%1,%2};" : "=l"(d) : "f"(x), "f"(y)); return d;
}
__device__ __forceinline__ float2 unpack2(ull a) {
    float2 r; asm("mov.b64 {%0,%1},%2;" : "=f"(r.x), "=f"(r.y) : "l"(a)); return r;
}
__device__ __forceinline__ float gelu_f(float yv) {
    float c_ = fmaf(0.044715f, yv * yv, 1.f);
    float q_ = -1.5957691216f * yv * c_;
    return __fdividef(yv, 1.f + __expf(q_));     // yv * sigmoid(2*0.79788*yv*c)
}

// ---------------------------------------------------------------------------
// Setup 1: SSM params + w^64; transpose+duplicate out_w; zero pooled. 32768 thr.
// ---------------------------------------------------------------------------
__global__ void setup_kernel(const float* __restrict__ log_dt,
                             const float* __restrict__ log_A_real,
                             const float* __restrict__ A_imag,
                             const float* __restrict__ C_re,
                             const float* __restrict__ C_im,
                             const float* __restrict__ out_w) {
    int i = blockIdx.x * blockDim.x + threadIdx.x;      // 0..32767
    {   // out_w row-major (2H,H): element [g][k] -> g_wt2[k][g] duplicated
        int g = i & 255, k = i >> 8;
        float v = out_w[g * H_ + k];
        g_wt2[k * G_ + g] = pack2(v, v);
    }
    if (i < H_ * N_) {
        int h = i >> 5;
        float dt = expf(log_dt[h]);
        float ar = -expf(log_A_real[i]);
        float ai = A_imag[i];
        float er = expf(dt * ar);
        float si, co;
        sincosf(dt * ai, &si, &co);
        float wr = er * co, wi = er * si;       // w = exp(dt*A)
        float inv = 1.f / (ar * ar + ai * ai);
        float dr = wr - 1.f;
        float qr = (dr * ar + wi * ai) * inv;   // (w-1)/A
        float qi = (wi * ar - dr * ai) * inv;
        float cr = C_re[i], ci = C_im[i];
        float kr = 2.f * (cr * qr - ci * qi);   // k = 2*C*(w-1)/A
        float ki = 2.f * (cr * qi + ci * qr);
        g_wk[i] = make_float4(wr, wi, kr, ki);
        float tr = wr, ti = wi;                  // w^64 by 6 squarings
        #pragma unroll
        for (int s = 0; s < 6; ++s) {
            float nr = tr * tr - ti * ti;
            ti = 2.f * tr * ti;
            tr = nr;
        }
        g_wT[i] = make_float2(tr, ti);
    }
    if (i < B_ * H_) g_pooled[i] = 0.f;
}

// ---------------------------------------------------------------------------
// Setup 2: per-head matrices.  A1[k][n]=Re(w^{63-k}), [k][32+n]=Im(w^{63-k}).
// A2[k<64][t]=kappa[t-k] (t>=k), A2[64+n][t]=Re(k w^{t+1}), A2[96+n][t]=-Im(k w^{t+1}).
// 128 blocks (head) x 64 threads.
// ---------------------------------------------------------------------------
__global__ void setup2_kernel() {
    __shared__ float wr[TC + 1][32], wim[TC + 1][32];
    __shared__ float skr[32], ski[32], kap[TC];
    int h = blockIdx.x, t = threadIdx.x;
    if (t < 32) {
        float4 wk = g_wk[h * N_ + t];
        skr[t] = wk.z; ski[t] = wk.w;
        float cr = 1.f, ci = 0.f;
        for (int d = 0; d <= TC; ++d) {
            wr[d][t] = cr; wim[d][t] = ci;
            float nr = cr * wk.x - ci * wk.y;
            ci = cr * wk.y + ci * wk.x;
            cr = nr;
        }
    }
    __syncthreads();
    {   // kappa[t] = Re(sum_n k_n w_n^t)
        float s = 0.f;
        #pragma unroll
        for (int n = 0; n < 32; ++n)
            s += skr[n] * wr[t][n] - ski[n] * wim[t][n];
        kap[t] = s;
    }
    __syncthreads();
    for (int idx = t; idx < TC * TC; idx += 64) {
        int k = idx >> 6, r = idx & 63, n = r & 31;
        float v = (r < 32) ? wr[63 - k][n] : wim[63 - k][n];
        g_A1[((size_t)h * TC + k) * TC + r] = pack2(v, v);
    }
    for (int idx = t; idx < 2 * TC * TC; idx += 64) {
        int k = idx >> 6, tt = idx & 63;
        float v;
        if (k < 64) v = (tt >= k) ? kap[tt - k] : 0.f;
        else if (k < 96) { int n = k - 64; v = skr[n] * wr[tt + 1][n] - ski[n] * wim[tt + 1][n]; }
        else             { int n = k - 96; v = -(skr[n] * wim[tt + 1][n] + ski[n] * wr[tt + 1][n]); }
        g_A2[((size_t)h * 2 * TC + k) * TC + tt] = pack2(v, v);
    }
}

// ---------------------------------------------------------------------------
// GEMM1: chunk finals  F[h][col][r] = sum_k A1[h][k][r] * u[k][col].
// Encoder fused (u computed from x into smem). Block = (head, 64-col tile).
// ---------------------------------------------------------------------------
__global__ void __launch_bounds__(256) gemm1_kernel(const float* __restrict__ x,
                                                    const float* __restrict__ enc_w,
                                                    const float* __restrict__ enc_b) {
    __shared__ float us[TC][68];
    int tid = threadIdx.x;
    int h = blockIdx.x >> 4;
    int tile = blockIdx.x & 15;
    int b = tile >> 1, j0 = (tile & 1) << 6;
    float e0 = enc_w[h], e1 = enc_w[H_ + h], eb = enc_b[h];
    const float2* xb = reinterpret_cast<const float2*>(x) + (size_t)b * L_ + j0 * TC;
    for (int m = tid; m < 4096; m += 256) {
        float2 xv = xb[m];
        us[m & 63][m >> 6] = fmaf(e1, xv.y, fmaf(e0, xv.x, eb));
    }
    __syncthreads();

    int tx = tid & 15, ty = tid >> 4;
    ull acc[4][2] = {};
    const ull* A = g_A1 + (size_t)h * TC * TC + 4 * tx;
    const float* vp = &us[0][4 * ty];
    #pragma unroll 4
    for (int k = 0; k < TC; ++k) {
        ulonglong2 a01 = *reinterpret_cast<const ulonglong2*>(A + (size_t)k * TC);
        ulonglong2 a23 = *reinterpret_cast<const ulonglong2*>(A + (size_t)k * TC + 2);
        ulonglong2 vv = *reinterpret_cast<const ulonglong2*>(vp + k * 68);
        acc[0][0]=fma2(a01.x,vv.x,acc[0][0]); acc[0][1]=fma2(a01.x,vv.y,acc[0][1]);
        acc[1][0]=fma2(a01.y,vv.x,acc[1][0]); acc[1][1]=fma2(a01.y,vv.y,acc[1][1]);
        acc[2][0]=fma2(a23.x,vv.x,acc[2][0]); acc[2][1]=fma2(a23.x,vv.y,acc[2][1]);
        acc[3][0]=fma2(a23.y,vv.x,acc[3][0]); acc[3][1]=fma2(a23.y,vv.y,acc[3][1]);
    }
    #pragma unroll
    for (int q = 0; q < 2; ++q) {
        float2 r0 = unpack2(acc[0][q]), r1 = unpack2(acc[1][q]);
        float2 r2 = unpack2(acc[2][q]), r3 = unpack2(acc[3][q]);
        int col = j0 + 4 * ty + 2 * q;
        size_t base = ((size_t)h * COLS + b * J_ + col) * TC + 4 * tx;
        *reinterpret_cast<float4*>(g_F + base)      = make_float4(r0.x, r1.x, r2.x, r3.x);
        *reinterpret_cast<float4*>(g_F + base + TC) = make_float4(r0.y, r1.y, r2.y, r3.y);
    }
}

// ---------------------------------------------------------------------------
// Chain: c(j+1) = w^64 (.) c(j) + f(j); writes c(j) per chunk. Warp per (b,h).
// ---------------------------------------------------------------------------
__global__ void chain_kernel() {
    int tid = threadIdx.x;
    int wid = tid >> 5, n = tid & 31;
    int pid = blockIdx.x * 8 + wid;              // 0..1023
    int b = pid >> 7, h = pid & 127;
    float2 wT = g_wT[h * N_ + n];
    float wTx = wT.x, wTy = wT.y;
    size_t base = ((size_t)h * COLS + b * J_) * TC;
    float cr = 0.f, ci = 0.f;
    for (int j = 0; j < J_; j += 4) {
        float fr[4], fi[4];
        #pragma unroll
        for (int q = 0; q < 4; ++q) {
            size_t ix = base + (size_t)(j + q) * TC;
            fr[q] = g_F[ix + n]; fi[q] = g_F[ix + 32 + n];
        }
        #pragma unroll
        for (int q = 0; q < 4; ++q) {
            size_t ix = base + (size_t)(j + q) * TC;
            g_C[ix + n] = cr; g_C[ix + 32 + n] = ci;
            float nr = fmaf(wTx, cr, fmaf(-wTy, ci, fr[q]));
            ci = fmaf(wTy, cr, fmaf(wTx, ci, fi[q]));
            cr = nr;
        }
    }
}

// ---------------------------------------------------------------------------
// GEMM2: y[t][col] = sum_{k<128} A2[h][k][t] * [u;c][k][col], + D*u, GELU.
// Block = (head, 64-col tile). Encoder fused again (u part of the B-tile).
// ---------------------------------------------------------------------------
__global__ void __launch_bounds__(256) gemm2_kernel(const float* __restrict__ x,
                                                    const float* __restrict__ enc_w,
                                                    const float* __restrict__ enc_b,
                                                    const float* __restrict__ D) {
    __shared__ float us[2 * TC][68];             // rows 0..63: u, 64..127: c
    int tid = threadIdx.x;
    int h = blockIdx.x >> 4;
    int tile = blockIdx.x & 15;
    int b = tile >> 1, j0 = (tile & 1) << 6;
    float e0 = enc_w[h], e1 = enc_w[H_ + h], eb = enc_b[h];
    const float2* xb = reinterpret_cast<const float2*>(x) + (size_t)b * L_ + j0 * TC;
    for (int m = tid; m < 4096; m += 256) {
        float2 xv = xb[m];
        us[m & 63][m >> 6] = fmaf(e1, xv.y, fmaf(e0, xv.x, eb));
    }
    const float* Cp = g_C + ((size_t)h * COLS + b * J_ + j0) * TC;
    for (int m = tid; m < 4096; m += 256)
        us[64 + (m & 63)][m >> 6] = Cp[m];
    __syncthreads();

    int tx = tid & 15, ty = tid >> 4;
    ull acc[4][2] = {};
    const ull* A = g_A2 + (size_t)h * 2 * TC * TC + 4 * tx;
    const float* vp = &us[0][4 * ty];
    #pragma unroll 4
    for (int k = 0; k < 2 * TC; ++k) {
        ulonglong2 a01 = *reinterpret_cast<const ulonglong2*>(A + (size_t)k * TC);
        ulonglong2 a23 = *reinterpret_cast<const ulonglong2*>(A + (size_t)k * TC + 2);
        ulonglong2 vv = *reinterpret_cast<const ulonglong2*>(vp + k * 68);
        acc[0][0]=fma2(a01.x,vv.x,acc[0][0]); acc[0][1]=fma2(a01.x,vv.y,acc[0][1]);
        acc[1][0]=fma2(a01.y,vv.x,acc[1][0]); acc[1][1]=fma2(a01.y,vv.y,acc[1][1]);
        acc[2][0]=fma2(a23.x,vv.x,acc[2][0]); acc[2][1]=fma2(a23.x,vv.y,acc[2][1]);
        acc[3][0]=fma2(a23.y,vv.x,acc[3][0]); acc[3][1]=fma2(a23.y,vv.y,acc[3][1]);
    }

    float Dh = D[h];
    float* yb = g_y + ((size_t)b * H_ + h) * L_;
    #pragma unroll
    for (int q = 0; q < 2; ++q) {
        float2 p0 = unpack2(acc[0][q]), p1 = unpack2(acc[1][q]);
        float2 p2 = unpack2(acc[2][q]), p3 = unpack2(acc[3][q]);
        #pragma unroll
        for (int s = 0; s < 2; ++s) {
            int col = 4 * ty + 2 * q + s;
            float v0 = s ? p0.y : p0.x, v1 = s ? p1.y : p1.x;
            float v2 = s ? p2.y : p2.x, v3 = s ? p3.y : p3.x;
            v0 = gelu_f(v0 + Dh * us[4 * tx + 0][col]);
            v1 = gelu_f(v1 + Dh * us[4 * tx + 1][col]);
            v2 = gelu_f(v2 + Dh * us[4 * tx + 2][col]);
            v3 = gelu_f(v3 + Dh * us[4 * tx + 3][col]);
            *reinterpret_cast<float4*>(yb + (size_t)(j0 + col) * TC + 4 * tx) =
                make_float4(v0, v1, v2, v3);
        }
    }
}

// ---------------------------------------------------------------------------
// GLU projection + pool (proven R3/R5 kernel, unchanged).
// ---------------------------------------------------------------------------
#define ROW(r, pa) { acc[r][0] = fma2((pa), v0, acc[r][0]); \
                     acc[r][1] = fma2((pa), v1, acc[r][1]); \
                     acc[r][2] = fma2((pa), v2, acc[r][2]); \
                     acc[r][3] = fma2((pa), v3, acc[r][3]); }

__global__ void __launch_bounds__(256, 2) glu_kernel(const float* __restrict__ out_b) {
    __shared__ float ys[H_ * 68];        // y tile [k][64 l], pad 68
    int tid = threadIdx.x;
    int tx = tid & 7;
    int ty = tid >> 3;
    int t = blockIdx.x;
    int b = t >> 7, l0 = (t & 127) << 6;

    float bA[4], bG[4];
    #pragma unroll
    for (int i = 0; i < 4; i++) { bA[i] = out_b[4 * ty + i]; bG[i] = out_b[H_ + 4 * ty + i]; }

    const float* yb = g_y + (size_t)b * H_ * L_;
    for (int i = tid; i < H_ * 16; i += 256) {
        int hh = i >> 4, lq = i & 15;
        float4 v = *reinterpret_cast<const float4*>(yb + (size_t)hh * L_ + l0 + lq * 4);
        *reinterpret_cast<float4*>(ys + hh * 68 + lq * 4) = v;
    }
    __syncthreads();

    ull acc[8][4];
    #pragma unroll
    for (int r = 0; r < 8; r++) {
        #pragma unroll
        for (int jj = 0; jj < 4; jj++) acc[r][jj] = 0ull;
    }

    #pragma unroll 4
    for (int k = 0; k < H_; ++k) {
        const ull* wa = g_wt2 + k * G_ + 4 * ty;
        ulonglong2 A0 = *reinterpret_cast<const ulonglong2*>(wa);
        ulonglong2 A1 = *reinterpret_cast<const ulonglong2*>(wa + 2);
        ulonglong2 G0 = *reinterpret_cast<const ulonglong2*>(wa + H_);
        ulonglong2 G1 = *reinterpret_cast<const ulonglong2*>(wa + H_ + 2);
        const float* yr = ys + k * 68;
        ulonglong2 V0 = *reinterpret_cast<const ulonglong2*>(yr + 4 * tx);
        ulonglong2 V1 = *reinterpret_cast<const ulonglong2*>(yr + 32 + 4 * tx);
        ull v0 = V0.x, v1 = V0.y, v2 = V1.x, v3 = V1.y;
        ROW(0, A0.x) ROW(1, A0.y) ROW(2, A1.x) ROW(3, A1.y)
        ROW(4, G0.x) ROW(5, G0.y) ROW(6, G1.x) ROW(7, G1.y)
    }

    #pragma unroll
    for (int i = 0; i < 4; i++) {
        float s = 0.f;
        #pragma unroll
        for (int jj = 0; jj < 4; jj++) {
            float2 za = unpack2(acc[i][jj]);
            float2 zg = unpack2(acc[4 + i][jj]);
            float a0 = za.x + bA[i], a1 = za.y + bA[i];
            float g0 = zg.x + bG[i], g1 = zg.y + bG[i];
            s += a0 * __fdividef(1.f, 1.f + __expf(-g0));
            s += a1 * __fdividef(1.f, 1.f + __expf(-g1));
        }
        atomicAdd(&g_pooled[b * H_ + 4 * ty + i], s);
    }
}

// ---------------------------------------------------------------------------
// Decode: out[b] = (pooled_sum[b,:]/L) . dec_w + dec_b
// ---------------------------------------------------------------------------
__global__ void decode_kernel(const float* __restrict__ dec_w,
                              const float* __restrict__ dec_b,
                              float* __restrict__ out) {
    int wid = threadIdx.x >> 5, lane = threadIdx.x & 31;
    int b = wid;
    float p = 0.f;
    #pragma unroll
    for (int i = 0; i < 4; i++) {
        int h = lane + 32 * i;
        p += g_pooled[b * H_ + h] * dec_w[h];
    }
    p += __shfl_xor_sync(0xffffffffu, p, 16);
    p += __shfl_xor_sync(0xffffffffu, p, 8);
    p += __shfl_xor_sync(0xffffffffu, p, 4);
    p += __shfl_xor_sync(0xffffffffu, p, 2);
    p += __shfl_xor_sync(0xffffffffu, p, 1);
    if (lane == 0) out[b] = p * (1.f / (float)L_) + dec_b[0];
}

// ---------------------------------------------------------------------------
extern "C" void kernel_launch(void* const* d_in, const int* in_sizes, int n_in,
                              void* d_out, int out_size) {
    const float* x      = (const float*)d_in[0];
    const float* enc_w  = (const float*)d_in[1];
    const float* enc_b  = (const float*)d_in[2];
    const float* log_dt = (const float*)d_in[3];
    const float* log_A  = (const float*)d_in[4];
    const float* A_im   = (const float*)d_in[5];
    const float* C_re   = (const float*)d_in[6];
    const float* C_im   = (const float*)d_in[7];
    const float* D      = (const float*)d_in[8];
    const float* out_w  = (const float*)d_in[9];
    const float* out_b  = (const float*)d_in[10];
    const float* dec_w  = (const float*)d_in[11];
    const float* dec_b  = (const float*)d_in[12];
    float* out = (float*)d_out;

    setup_kernel<<<128, 256>>>(log_dt, log_A, A_im, C_re, C_im, out_w);
    setup2_kernel<<<128, 64>>>();
    gemm1_kernel<<<2048, 256>>>(x, enc_w, enc_b);
    chain_kernel<<<128, 256>>>();
    gemm2_kernel<<<2048, 256>>>(x, enc_w, enc_b, D);
    glu_kernel<<<1024, 256>>>(out_b);
    decode_kernel<<<1, 256>>>(dec_w, dec_b, out);
}

// round 9
// speedup vs baseline: 1.4784x; 1.4784x over previous
#include <cuda_runtime.h>
#include <cstdint>

#define B_ 8
#define L_ 8192
#define H_ 128
#define N_ 32
#define G_ 256   /* 2H */
#define TC 64    /* chunk length */
#define J_ 128   /* chunks per sequence */

typedef unsigned long long ull;

// Scratch (static __device__ arrays: no allocation anywhere)
__device__ float4 g_wk[H_ * N_];                        // {w_re, w_im, k_re, k_im}
__device__ float2 g_wT[H_ * N_];                        // w^64
__device__ __align__(16) float g_A1f[(size_t)H_ * TC * TC];      // finals matrix [h][k][r]
__device__ __align__(16) float g_A2f[(size_t)H_ * 2 * TC * TC];  // [Tri+D | V]   [h][k][t]
__device__ float  g_y[(size_t)B_ * H_ * L_];            // post-GELU activations (B,H,L)
__device__ __align__(16) ull g_wt2[H_ * G_];            // out_w transposed + dup'd
__device__ float  g_pooled[B_ * H_];

__device__ __forceinline__ ull fma2(ull a, ull b, ull c) {
    ull d; asm("fma.rn.f32x2 %0,%1,%2,%3;" : "=l"(d) : "l"(a), "l"(b), "l"(c)); return d;
}
__device__ __forceinline__ ull pack2(float x, float y) {
    ull d; asm("mov.b64 %0,{%1,%2};" : "=l"(d) : "f"(x), "f"(y)); return d;
}
__device__ __forceinline__ float2 unpack2(ull a) {
    float2 r; asm("mov.b64 {%0,%1},%2;" : "=f"(r.x), "=f"(r.y) : "l"(a)); return r;
}
__device__ __forceinline__ float gelu_f(float yv) {
    float c_ = fmaf(0.044715f, yv * yv, 1.f);
    float q_ = -1.5957691216f * yv * c_;
    return __fdividef(yv, 1.f + __expf(q_));            // yv * sigmoid(2*0.79788*yv*c)
}

// ---------------------------------------------------------------------------
// Setup 1: SSM params + w^64; transpose+duplicate out_w; zero pooled. 32768 thr.
// ---------------------------------------------------------------------------
__global__ void setup_kernel(const float* __restrict__ log_dt,
                             const float* __restrict__ log_A_real,
                             const float* __restrict__ A_imag,
                             const float* __restrict__ C_re,
                             const float* __restrict__ C_im,
                             const float* __restrict__ out_w) {
    int i = blockIdx.x * blockDim.x + threadIdx.x;      // 0..32767
    {   // out_w row-major (2H,H): element [g][k] -> g_wt2[k][g] duplicated
        int g = i & 255, k = i >> 8;
        float v = out_w[g * H_ + k];
        g_wt2[k * G_ + g] = pack2(v, v);
    }
    if (i < H_ * N_) {
        int h = i >> 5;
        float dt = expf(log_dt[h]);
        float ar = -expf(log_A_real[i]);
        float ai = A_imag[i];
        float er = expf(dt * ar);
        float si, co;
        sincosf(dt * ai, &si, &co);
        float wr = er * co, wi = er * si;       // w = exp(dt*A)
        float inv = 1.f / (ar * ar + ai * ai);
        float dr = wr - 1.f;
        float qr = (dr * ar + wi * ai) * inv;   // (w-1)/A
        float qi = (wi * ar - dr * ai) * inv;
        float cr = C_re[i], ci = C_im[i];
        float kr = 2.f * (cr * qr - ci * qi);   // k = 2*C*(w-1)/A
        float ki = 2.f * (cr * qi + ci * qr);
        g_wk[i] = make_float4(wr, wi, kr, ki);
        float tr = wr, ti = wi;                  // w^64 by 6 squarings
        #pragma unroll
        for (int s = 0; s < 6; ++s) {
            float nr = tr * tr - ti * ti;
            ti = 2.f * tr * ti;
            tr = nr;
        }
        g_wT[i] = make_float2(tr, ti);
    }
    if (i < B_ * H_) g_pooled[i] = 0.f;
}

// ---------------------------------------------------------------------------
// Setup 2: per-head matrices (plain floats, row-major [k][r]).
// A1[k][n]=Re(w^{63-k}), A1[k][32+n]=Im(w^{63-k}).
// A2[k<64][t]=kappa[t-k] (t>k), diag gets +D; A2[64+n][t]=Re(k w^{t+1});
// A2[96+n][t]=-Im(k w^{t+1}).  128 blocks (head) x 64 threads.
// ---------------------------------------------------------------------------
__global__ void setup2_kernel(const float* __restrict__ D) {
    __shared__ float wr[TC + 1][32], wim[TC + 1][32];
    __shared__ float skr[32], ski[32], kap[TC];
    int h = blockIdx.x, t = threadIdx.x;
    if (t < 32) {
        float4 wk = g_wk[h * N_ + t];
        skr[t] = wk.z; ski[t] = wk.w;
        float cr = 1.f, ci = 0.f;
        for (int d = 0; d <= TC; ++d) {
            wr[d][t] = cr; wim[d][t] = ci;
            float nr = cr * wk.x - ci * wk.y;
            ci = cr * wk.y + ci * wk.x;
            cr = nr;
        }
    }
    __syncthreads();
    {   // kappa[t] = Re(sum_n k_n w_n^t)
        float s = 0.f;
        #pragma unroll
        for (int n = 0; n < 32; ++n)
            s += skr[n] * wr[t][n] - ski[n] * wim[t][n];
        kap[t] = s;
    }
    __syncthreads();
    float Dh = D[h];
    for (int idx = t; idx < TC * TC; idx += 64) {
        int k = idx >> 6, r = idx & 63, n = r & 31;
        g_A1f[((size_t)h * TC + k) * TC + r] = (r < 32) ? wr[63 - k][n] : wim[63 - k][n];
    }
    for (int idx = t; idx < 2 * TC * TC; idx += 64) {
        int k = idx >> 6, tt = idx & 63;
        float v;
        if (k < 64)      v = (tt > k) ? kap[tt - k] : (tt == k ? kap[0] + Dh : 0.f);
        else if (k < 96) { int n = k - 64; v = skr[n] * wr[tt + 1][n] - ski[n] * wim[tt + 1][n]; }
        else             { int n = k - 96; v = -(skr[n] * wim[tt + 1][n] + ski[n] * wr[tt + 1][n]); }
        g_A2f[((size_t)h * 2 * TC + k) * TC + tt] = v;
    }
}

// ---------------------------------------------------------------------------
// Fused SSM: block = (h, b), 256 threads, 196 KB dyn smem.
//   stage A: GEMM1  F[r][col] = sum_k A1[k][r] * u[k][col]       (64x128x64)
//   stage B: in-smem carry chain over 128 chunks (warp 0)
//   stage C: GEMM2  y[t][col] = sum_k A2[k][t] * [u;c][k][col]   (64x128x128)
//            epilogue: GELU (D folded into A2 diag), STG y.
// Rows packed in f32x2 lanes -> A operand plain floats (LDS.128 = 2 row-pairs),
// only [u;c] stored duplicated.
// ---------------------------------------------------------------------------
#define SB_STRIDE 130      /* ull stride, even -> 16B-aligned rows */
#define SFC_STRIDE 68
#define SMEM_BYTES 200704  /* 32768 (A) + 133120 (sB) + 34816 (sFC) */

#define GBODY {                                                              \
    ulonglong2 a = *reinterpret_cast<const ulonglong2*>(ap);                 \
    ulonglong2 u01 = *reinterpret_cast<const ulonglong2*>(up);               \
    ulonglong2 u23 = *reinterpret_cast<const ulonglong2*>(up + 2);           \
    ulonglong2 u45 = *reinterpret_cast<const ulonglong2*>(up + 4);           \
    ulonglong2 u67 = *reinterpret_cast<const ulonglong2*>(up + 6);           \
    acc[0][0]=fma2(a.x,u01.x,acc[0][0]); acc[1][0]=fma2(a.y,u01.x,acc[1][0]);\
    acc[0][1]=fma2(a.x,u01.y,acc[0][1]); acc[1][1]=fma2(a.y,u01.y,acc[1][1]);\
    acc[0][2]=fma2(a.x,u23.x,acc[0][2]); acc[1][2]=fma2(a.y,u23.x,acc[1][2]);\
    acc[0][3]=fma2(a.x,u23.y,acc[0][3]); acc[1][3]=fma2(a.y,u23.y,acc[1][3]);\
    acc[0][4]=fma2(a.x,u45.x,acc[0][4]); acc[1][4]=fma2(a.y,u45.x,acc[1][4]);\
    acc[0][5]=fma2(a.x,u45.y,acc[0][5]); acc[1][5]=fma2(a.y,u45.y,acc[1][5]);\
    acc[0][6]=fma2(a.x,u67.x,acc[0][6]); acc[1][6]=fma2(a.y,u67.x,acc[1][6]);\
    acc[0][7]=fma2(a.x,u67.y,acc[0][7]); acc[1][7]=fma2(a.y,u67.y,acc[1][7]);\
    ap += TC; up += SB_STRIDE;                                               \
}

__global__ void __launch_bounds__(256) ssm_kernel(const float* __restrict__ x,
                                                  const float* __restrict__ enc_w,
                                                  const float* __restrict__ enc_b) {
    extern __shared__ char smem[];
    float* sA  = reinterpret_cast<float*>(smem);                 // [k][64 r/t]
    ull*   sB  = reinterpret_cast<ull*>(smem + 32768);           // [k][128 col] dup'd
    float* sFC = reinterpret_cast<float*>(smem + 165888);        // [col][64 r]
    int tid = threadIdx.x;
    int tx = tid & 15, ty = tid >> 4;    // rows 4tx..4tx+3, cols 8ty..8ty+7
    int h = blockIdx.x >> 3, b = blockIdx.x & 7;

    // ---- fill u (dup'd) rows 0..63 of sB; encoder fused ----
    float e0 = enc_w[h], e1 = enc_w[H_ + h], eb = enc_b[h];
    const float2* xb = reinterpret_cast<const float2*>(x) + (size_t)b * L_;
    #pragma unroll
    for (int m = tid; m < 8192; m += 256) {
        float2 xv = xb[m];
        float u = fmaf(e1, xv.y, fmaf(e0, xv.x, eb));
        sB[(size_t)(m & 63) * SB_STRIDE + (m >> 6)] = pack2(u, u);
    }
    // ---- load A1 (4096 floats) ----
    {
        const float4* A1p = reinterpret_cast<const float4*>(g_A1f + (size_t)h * TC * TC);
        float4* sA4 = reinterpret_cast<float4*>(sA);
        #pragma unroll
        for (int m = tid; m < 1024; m += 256) sA4[m] = A1p[m];
    }
    __syncthreads();

    // ---- GEMM1: F = A1 * u ----
    ull acc[2][8];
    #pragma unroll
    for (int c = 0; c < 8; ++c) { acc[0][c] = 0ull; acc[1][c] = 0ull; }
    {
        const float* ap = sA + 4 * tx;
        const ull* up = sB + 8 * ty;
        #pragma unroll 4
        for (int k = 0; k < TC; ++k) GBODY
    }
    #pragma unroll
    for (int c = 0; c < 8; ++c) {
        float2 r0 = unpack2(acc[0][c]), r1 = unpack2(acc[1][c]);
        *reinterpret_cast<float4*>(sFC + (8 * ty + c) * SFC_STRIDE + 4 * tx) =
            make_float4(r0.x, r0.y, r1.x, r1.y);
    }
    __syncthreads();

    // ---- load A2 (8192 floats) while warp 0 runs the carry chain ----
    {
        const float4* A2p = reinterpret_cast<const float4*>(g_A2f + (size_t)h * 2 * TC * TC);
        float4* sA4 = reinterpret_cast<float4*>(sA);
        #pragma unroll
        for (int m = tid; m < 2048; m += 256) sA4[m] = A2p[m];
    }
    if (tid < 32) {          // chain: c(j) = w^64 c(j-1) + f(j-1), overwrite F->C
        float2 wT = g_wT[h * N_ + tid];
        float wTx = wT.x, wTy = wT.y;
        float cr = 0.f, ci = 0.f;
        float* fr0 = sFC + tid;
        float* fi0 = sFC + 32 + tid;
        for (int j = 0; j < J_; j += 4) {
            float fr[4], fi[4];
            #pragma unroll
            for (int q = 0; q < 4; ++q) {
                fr[q] = fr0[(j + q) * SFC_STRIDE];
                fi[q] = fi0[(j + q) * SFC_STRIDE];
            }
            #pragma unroll
            for (int q = 0; q < 4; ++q) {
                fr0[(j + q) * SFC_STRIDE] = cr;
                fi0[(j + q) * SFC_STRIDE] = ci;
                float nr = fmaf(wTx, cr, fmaf(-wTy, ci, fr[q]));
                ci = fmaf(wTy, cr, fmaf(wTx, ci, fi[q]));
                cr = nr;
            }
        }
    }
    __syncthreads();

    // ---- dup carries into sB rows 64..127 ----
    #pragma unroll
    for (int m = tid; m < 8192; m += 256) {
        float v = sFC[(m >> 6) * SFC_STRIDE + (m & 63)];
        sB[(size_t)(64 + (m & 63)) * SB_STRIDE + (m >> 6)] = pack2(v, v);
    }
    __syncthreads();

    // ---- GEMM2: y = A2 * [u;c], then GELU ----
    #pragma unroll
    for (int c = 0; c < 8; ++c) { acc[0][c] = 0ull; acc[1][c] = 0ull; }
    {
        const float* ap = sA + 4 * tx;
        const ull* up = sB + 8 * ty;
        #pragma unroll 4
        for (int k = 0; k < 2 * TC; ++k) GBODY
    }
    float* yb = g_y + ((size_t)b * H_ + h) * L_;
    #pragma unroll
    for (int c = 0; c < 8; ++c) {
        int col = 8 * ty + c;
        float2 r0 = unpack2(acc[0][c]), r1 = unpack2(acc[1][c]);
        float4 o = make_float4(gelu_f(r0.x), gelu_f(r0.y), gelu_f(r1.x), gelu_f(r1.y));
        *reinterpret_cast<float4*>(yb + (size_t)col * TC + 4 * tx) = o;
    }
}

// ---------------------------------------------------------------------------
// GLU projection + pool (proven kernel, unchanged).
// ---------------------------------------------------------------------------
#define ROW(r, pa) { acc[r][0] = fma2((pa), v0, acc[r][0]); \
                     acc[r][1] = fma2((pa), v1, acc[r][1]); \
                     acc[r][2] = fma2((pa), v2, acc[r][2]); \
                     acc[r][3] = fma2((pa), v3, acc[r][3]); }

__global__ void __launch_bounds__(256, 2) glu_kernel(const float* __restrict__ out_b) {
    __shared__ float ys[H_ * 68];        // y tile [k][64 l], pad 68
    int tid = threadIdx.x;
    int tx = tid & 7;
    int ty = tid >> 3;
    int t = blockIdx.x;
    int b = t >> 7, l0 = (t & 127) << 6;

    float bA[4], bG[4];
    #pragma unroll
    for (int i = 0; i < 4; i++) { bA[i] = out_b[4 * ty + i]; bG[i] = out_b[H_ + 4 * ty + i]; }

    const float* yb = g_y + (size_t)b * H_ * L_;
    for (int i = tid; i < H_ * 16; i += 256) {
        int hh = i >> 4, lq = i & 15;
        float4 v = *reinterpret_cast<const float4*>(yb + (size_t)hh * L_ + l0 + lq * 4);
        *reinterpret_cast<float4*>(ys + hh * 68 + lq * 4) = v;
    }
    __syncthreads();

    ull acc[8][4];
    #pragma unroll
    for (int r = 0; r < 8; r++) {
        #pragma unroll
        for (int jj = 0; jj < 4; jj++) acc[r][jj] = 0ull;
    }

    #pragma unroll 4
    for (int k = 0; k < H_; ++k) {
        const ull* wa = g_wt2 + k * G_ + 4 * ty;
        ulonglong2 A0 = *reinterpret_cast<const ulonglong2*>(wa);
        ulonglong2 A1 = *reinterpret_cast<const ulonglong2*>(wa + 2);
        ulonglong2 G0 = *reinterpret_cast<const ulonglong2*>(wa + H_);
        ulonglong2 G1 = *reinterpret_cast<const ulonglong2*>(wa + H_ + 2);
        const float* yr = ys + k * 68;
        ulonglong2 V0 = *reinterpret_cast<const ulonglong2*>(yr + 4 * tx);
        ulonglong2 V1 = *reinterpret_cast<const ulonglong2*>(yr + 32 + 4 * tx);
        ull v0 = V0.x, v1 = V0.y, v2 = V1.x, v3 = V1.y;
        ROW(0, A0.x) ROW(1, A0.y) ROW(2, A1.x) ROW(3, A1.y)
        ROW(4, G0.x) ROW(5, G0.y) ROW(6, G1.x) ROW(7, G1.y)
    }

    #pragma unroll
    for (int i = 0; i < 4; i++) {
        float s = 0.f;
        #pragma unroll
        for (int jj = 0; jj < 4; jj++) {
            float2 za = unpack2(acc[i][jj]);
            float2 zg = unpack2(acc[4 + i][jj]);
            float a0 = za.x + bA[i], a1 = za.y + bA[i];
            float g0 = zg.x + bG[i], g1 = zg.y + bG[i];
            s += a0 * __fdividef(1.f, 1.f + __expf(-g0));
            s += a1 * __fdividef(1.f, 1.f + __expf(-g1));
        }
        atomicAdd(&g_pooled[b * H_ + 4 * ty + i], s);
    }
}

// ---------------------------------------------------------------------------
// Decode: out[b] = (pooled_sum[b,:]/L) . dec_w + dec_b
// ---------------------------------------------------------------------------
__global__ void decode_kernel(const float* __restrict__ dec_w,
                              const float* __restrict__ dec_b,
                              float* __restrict__ out) {
    int wid = threadIdx.x >> 5, lane = threadIdx.x & 31;
    int b = wid;
    float p = 0.f;
    #pragma unroll
    for (int i = 0; i < 4; i++) {
        int h = lane + 32 * i;
        p += g_pooled[b * H_ + h] * dec_w[h];
    }
    p += __shfl_xor_sync(0xffffffffu, p, 16);
    p += __shfl_xor_sync(0xffffffffu, p, 8);
    p += __shfl_xor_sync(0xffffffffu, p, 4);
    p += __shfl_xor_sync(0xffffffffu, p, 2);
    p += __shfl_xor_sync(0xffffffffu, p, 1);
    if (lane == 0) out[b] = p * (1.f / (float)L_) + dec_b[0];
}

// ---------------------------------------------------------------------------
extern "C" void kernel_launch(void* const* d_in, const int* in_sizes, int n_in,
                              void* d_out, int out_size) {
    const float* x      = (const float*)d_in[0];
    const float* enc_w  = (const float*)d_in[1];
    const float* enc_b  = (const float*)d_in[2];
    const float* log_dt = (const float*)d_in[3];
    const float* log_A  = (const float*)d_in[4];
    const float* A_im   = (const float*)d_in[5];
    const float* C_re   = (const float*)d_in[6];
    const float* C_im   = (const float*)d_in[7];
    const float* D      = (const float*)d_in[8];
    const float* out_w  = (const float*)d_in[9];
    const float* out_b  = (const float*)d_in[10];
    const float* dec_w  = (const float*)d_in[11];
    const float* dec_b  = (const float*)d_in[12];
    float* out = (float*)d_out;

    cudaFuncSetAttribute(ssm_kernel, cudaFuncAttributeMaxDynamicSharedMemorySize,
                         SMEM_BYTES);

    setup_kernel<<<128, 256>>>(log_dt, log_A, A_im, C_re, C_im, out_w);
    setup2_kernel<<<128, 64>>>(D);
    ssm_kernel<<<1024, 256, SMEM_BYTES>>>(x, enc_w, enc_b);
    glu_kernel<<<1024, 256>>>(out_b);
    decode_kernel<<<1, 256>>>(dec_w, dec_b, out);
}